// round 2
// baseline (speedup 1.0000x reference)
#include <cuda_runtime.h>

typedef unsigned long long u64;

#define B_TOT   256
#define IN_CAPS 1152
#define KDIM    8
#define NCAPS   10
#define DDIM    16
#define CHUNKS  36
#define I_PER   32
#define BGROUPS 4
#define B_PER   64
#define SND     (B_TOT*NCAPS*DDIM)      /* 40960 */

// ---------------- scratch (static device memory, no allocs) ----------------
__device__ float g_Wt[NCAPS*IN_CAPS*128];        // W transposed: [n][i][k][d]
__device__ float g_spart[CHUNKS*SND];            // per-chunk partial s
__device__ float g_b[NCAPS*IN_CAPS*B_TOT];       // routing logits, layout [n][i][b]
__device__ float g_v[SND];                       // v between iterations [b][n][d]

// ---------------- f32x2 helpers (ptxas won't auto-fuse) ----------------
__device__ __forceinline__ u64 pk2(float x, float y){
    u64 r; asm("mov.b64 %0,{%1,%2};" : "=l"(r) : "f"(x), "f"(y)); return r;
}
__device__ __forceinline__ void upk2(u64 a, float& x, float& y){
    asm("mov.b64 {%0,%1},%2;" : "=f"(x), "=f"(y) : "l"(a));
}
__device__ __forceinline__ u64 ffma2(u64 a, u64 b, u64 c){
    u64 d; asm("fma.rn.f32x2 %0,%1,%2,%3;" : "=l"(d) : "l"(a), "l"(b), "l"(c)); return d;
}
__device__ __forceinline__ u64 fmul2(u64 a, u64 b){
    u64 d; asm("mul.rn.f32x2 %0,%1,%2;" : "=l"(d) : "l"(a), "l"(b)); return d;
}
__device__ __forceinline__ u64 fadd2(u64 a, u64 b){
    u64 d; asm("add.rn.f32x2 %0,%1,%2;" : "=l"(d) : "l"(a), "l"(b)); return d;
}

// ---------------- W transpose: [n][i][d][k] -> [n][i][k][d] ----------------
__global__ void k_transpose(const float* __restrict__ W){
    int idx = blockIdx.x * 256 + threadIdx.x;
    if (idx >= NCAPS*IN_CAPS*128) return;
    int k  = idx & 7;
    int d  = (idx >> 3) & 15;
    int ni = idx >> 7;
    g_Wt[(ni << 7) | (k << 4) | d] = W[idx];
}

// ---------------- main pass kernel ----------------
// PASS 0: c = 0.1 uniform (softmax of zeros) -> pure accumulation of tu.
// PASS 1: logit = tu.v0           (b was 0), write b, softmax, accumulate c*tu
// PASS 2: logit = b_old + tu.v1,  write b, softmax, accumulate
// PASS 3: logit = b_old + tu.v2,  no write,  softmax, accumulate
template<int PASS>
__global__ void __launch_bounds__(320, 1) k_pass(const float* __restrict__ x){
    __shared__ __align__(16) float ws[2][NCAPS*128];   // double-buffered Wt tile
    __shared__ float ex[NCAPS][64];                    // exp(logit) exchange
    __shared__ float red[64];                          // 1/sum per batch

    const int tid   = threadIdx.x;
    const int n     = tid >> 5;          // warp = output capsule
    const int lane  = tid & 31;
    const int chunk = blockIdx.x;
    const int bg    = blockIdx.y;
    const int i0    = chunk * I_PER;
    const int b0    = bg * B_PER + lane;
    const int b1    = b0 + 32;

    u64 v0[8], v1[8];
    if (PASS > 0){
        const u64* vp0 = (const u64*)&g_v[(b0*NCAPS + n)*DDIM];
        const u64* vp1 = (const u64*)&g_v[(b1*NCAPS + n)*DDIM];
        #pragma unroll
        for (int p = 0; p < 8; p++){ v0[p] = vp0[p]; v1[p] = vp1[p]; }
    }
    u64 s0[8], s1[8];
    #pragma unroll
    for (int p = 0; p < 8; p++){ s0[p] = 0ull; s1[p] = 0ull; }

    // cooperative Wt tile load: warp n loads its own 128-float row slice
    const float4* wsrc = (const float4*)&g_Wt[(n*IN_CAPS + i0)*128 + lane*4];
    *(float4*)&ws[0][n*128 + lane*4] = *wsrc;
    wsrc += 32;                                    // advance one i (128 floats)
    __syncthreads();

    const float* xp0 = x + (size_t)b0 * (IN_CAPS*KDIM) + (size_t)i0 * KDIM;
    const float* xp1 = x + (size_t)b1 * (IN_CAPS*KDIM) + (size_t)i0 * KDIM;
    float* bp = g_b + (n*IN_CAPS + i0)*B_TOT + bg*B_PER + lane;

    float* wcur = &ws[0][0];
    float* wnxt = &ws[1][0];

    for (int ii = 0; ii < I_PER; ii++){
        const bool havew = (ii + 1 < I_PER);
        float4 wpre;
        if (havew) wpre = *wsrc;

        float4 xa = *(const float4*)(xp0);
        float4 xb = *(const float4*)(xp0 + 4);
        float4 xc = *(const float4*)(xp1);
        float4 xd = *(const float4*)(xp1 + 4);
        xp0 += 8; xp1 += 8;
        float X0[8] = {xa.x,xa.y,xa.z,xa.w, xb.x,xb.y,xb.z,xb.w};
        float X1[8] = {xc.x,xc.y,xc.z,xc.w, xd.x,xd.y,xd.z,xd.w};

        // tu = sum_k Wt[k][:] * x_k   (f32x2 over d-pairs, two batches share W)
        u64 a0[8], a1[8];
        const u64* wrow = (const u64*)(wcur + n*128);
        #pragma unroll
        for (int k = 0; k < 8; k++){
            u64 xk0 = pk2(X0[k], X0[k]);
            u64 xk1 = pk2(X1[k], X1[k]);
            const ulonglong2* w2 = (const ulonglong2*)(wrow + k*8);
            #pragma unroll
            for (int q = 0; q < 4; q++){
                ulonglong2 w = w2[q];
                if (k == 0){
                    a0[2*q]   = fmul2(w.x, xk0); a0[2*q+1] = fmul2(w.y, xk0);
                    a1[2*q]   = fmul2(w.x, xk1); a1[2*q+1] = fmul2(w.y, xk1);
                } else {
                    a0[2*q]   = ffma2(w.x, xk0, a0[2*q]);   a0[2*q+1] = ffma2(w.y, xk0, a0[2*q+1]);
                    a1[2*q]   = ffma2(w.x, xk1, a1[2*q]);   a1[2*q+1] = ffma2(w.y, xk1, a1[2*q+1]);
                }
            }
        }

        float e0 = 0.f, e1 = 0.f;
        if (PASS > 0){
            // agreement logit = (b_old) + tu . v
            u64 d0 = fmul2(a0[0], v0[0]);
            u64 d1 = fmul2(a1[0], v1[0]);
            #pragma unroll
            for (int p = 1; p < 8; p++){ d0 = ffma2(a0[p], v0[p], d0); d1 = ffma2(a1[p], v1[p], d1); }
            float l0,h0,l1,h1; upk2(d0,l0,h0); upk2(d1,l1,h1);
            float dot0 = l0 + h0, dot1 = l1 + h1;
            if (PASS > 1){ dot0 += bp[0]; dot1 += bp[32]; }
            if (PASS < 3){ bp[0] = dot0; bp[32] = dot1; }
            bp += B_TOT;
            // logits are tiny (|b| < ~0.5) -> exp without max-subtraction is safe
            e0 = __expf(dot0); e1 = __expf(dot1);
            ex[n][lane]      = e0;
            ex[n][lane + 32] = e1;
            __syncthreads();
            if (tid < 64){
                float sm = ex[0][tid];
                #pragma unroll
                for (int j = 1; j < NCAPS; j++) sm += ex[j][tid];
                red[tid] = __fdividef(1.0f, sm);
            }
        }

        if (havew){ *(float4*)(wnxt + n*128 + lane*4) = wpre; wsrc += 32; }
        __syncthreads();
        { float* t = wcur; wcur = wnxt; wnxt = t; }

        if (PASS > 0){
            float c0 = e0 * red[lane];
            float c1 = e1 * red[lane + 32];
            u64 cc0 = pk2(c0, c0), cc1 = pk2(c1, c1);
            #pragma unroll
            for (int p = 0; p < 8; p++){
                s0[p] = ffma2(a0[p], cc0, s0[p]);
                s1[p] = ffma2(a1[p], cc1, s1[p]);
            }
        } else {
            #pragma unroll
            for (int p = 0; p < 8; p++){ s0[p] = fadd2(s0[p], a0[p]); s1[p] = fadd2(s1[p], a1[p]); }
        }
    }

    // write per-chunk partial s (deterministic, no atomics)
    float* sp0 = g_spart + ((size_t)(chunk*B_TOT + b0)*NCAPS + n)*DDIM;
    float* sp1 = g_spart + ((size_t)(chunk*B_TOT + b1)*NCAPS + n)*DDIM;
    #pragma unroll
    for (int q = 0; q < 4; q++){
        ((ulonglong2*)sp0)[q] = make_ulonglong2(s0[2*q], s0[2*q+1]);
        ((ulonglong2*)sp1)[q] = make_ulonglong2(s1[2*q], s1[2*q+1]);
    }
}

// ---------------- reduce partials + squash ----------------
template<bool FINAL>
__global__ void k_reduce(float* __restrict__ out, float scale){
    int g = blockIdx.x * 256 + threadIdx.x;      // over [b][n][d] = 40960
    float s = 0.f;
    #pragma unroll
    for (int c = 0; c < CHUNKS; c++) s += g_spart[(size_t)c*SND + g];
    s *= scale;
    float sq = s * s;
    sq += __shfl_xor_sync(0xffffffffu, sq, 1);
    sq += __shfl_xor_sync(0xffffffffu, sq, 2);
    sq += __shfl_xor_sync(0xffffffffu, sq, 4);
    sq += __shfl_xor_sync(0xffffffffu, sq, 8);
    float nrm = sqrtf(sq);
    float vv = (sq / (1.0f + sq)) * (s / (nrm + 1e-8f));
    if (FINAL) out[g] = vv;
    else       g_v[g] = vv;
}

// ---------------- launch ----------------
extern "C" void kernel_launch(void* const* d_in, const int* in_sizes, int n_in,
                              void* d_out, int out_size){
    const float* x = (const float*)d_in[0];
    const float* W = (const float*)d_in[1];
    if (n_in >= 2 && in_sizes[0] == NCAPS*IN_CAPS*128){   // defensive order swap
        const float* t = x; x = W; W = t;
    }
    float* out = (float*)d_out;

    dim3 pg(CHUNKS, BGROUPS);
    k_transpose<<<(NCAPS*IN_CAPS*128 + 255)/256, 256>>>(W);

    k_pass<0><<<pg, 320>>>(x);
    k_reduce<false><<<SND/256, 256>>>(nullptr, 0.1f);   // c = softmax(0) = 1/10

    k_pass<1><<<pg, 320>>>(x);
    k_reduce<false><<<SND/256, 256>>>(nullptr, 1.0f);

    k_pass<2><<<pg, 320>>>(x);
    k_reduce<false><<<SND/256, 256>>>(nullptr, 1.0f);

    k_pass<3><<<pg, 320>>>(x);
    k_reduce<true><<<SND/256, 256>>>(out, 1.0f);
}

// round 3
// speedup vs baseline: 1.2834x; 1.2834x over previous
#include <cuda_runtime.h>

typedef unsigned long long u64;
typedef unsigned int u32;

#define B_TOT   256
#define IN_CAPS 1152
#define KDIM    8
#define NCAPS   10
#define DDIM    16
#define CHUNKS  36
#define I_PER   32
#define BGROUPS 8
#define SND     (B_TOT*NCAPS*DDIM)      /* 40960 */
#define FDIM    (IN_CAPS*KDIM)          /* 9216  */

// ---------------- scratch (static device memory, no allocs) ----------------
__device__ float g_Wt[NCAPS*IN_CAPS*128];        // W transposed: [n][i][k][d]
__device__ float g_xT[FDIM*B_TOT];               // x transposed: [i*8+k][b]
__device__ float g_spart[CHUNKS*SND];            // per-chunk partial s
__device__ float g_b[NCAPS*IN_CAPS*B_TOT];       // routing logits [n][i][b]
__device__ float g_v[SND];                       // v between iterations [b][n][d]

// ---------------- f32x2 helpers ----------------
__device__ __forceinline__ u64 pk2(float x, float y){
    u64 r; asm("mov.b64 %0,{%1,%2};" : "=l"(r) : "f"(x), "f"(y)); return r;
}
__device__ __forceinline__ void upk2(u64 a, float& x, float& y){
    asm("mov.b64 {%0,%1},%2;" : "=f"(x), "=f"(y) : "l"(a));
}
__device__ __forceinline__ u64 ffma2(u64 a, u64 b, u64 c){
    u64 d; asm("fma.rn.f32x2 %0,%1,%2,%3;" : "=l"(d) : "l"(a), "l"(b), "l"(c)); return d;
}
__device__ __forceinline__ u64 fmul2(u64 a, u64 b){
    u64 d; asm("mul.rn.f32x2 %0,%1,%2;" : "=l"(d) : "l"(a), "l"(b)); return d;
}
__device__ __forceinline__ u64 fadd2(u64 a, u64 b){
    u64 d; asm("add.rn.f32x2 %0,%1,%2;" : "=l"(d) : "l"(a), "l"(b)); return d;
}
__device__ __forceinline__ u32 smemu32(const void* p){
    u32 a; asm("{ .reg .u64 t; cvta.to.shared.u64 t, %1; cvt.u32.u64 %0, t; }" : "=r"(a) : "l"(p));
    return a;
}
__device__ __forceinline__ void cpasync16(u32 dst, const void* src){
    asm volatile("cp.async.ca.shared.global [%0],[%1],16;" :: "r"(dst), "l"(src));
}
__device__ __forceinline__ void cpcommit(){ asm volatile("cp.async.commit_group;"); }
__device__ __forceinline__ void cpwait1(){ asm volatile("cp.async.wait_group 1;"); }

// ---------------- W transpose: [n][i][d][k] -> [n][i][k][d] ----------------
__global__ void k_wt(const float* __restrict__ W){
    int idx = blockIdx.x * 256 + threadIdx.x;
    if (idx >= NCAPS*IN_CAPS*128) return;
    int k  = idx & 7;
    int d  = (idx >> 3) & 15;
    int ni = idx >> 7;
    g_Wt[(ni << 7) | (k << 4) | d] = W[idx];
}

// ---------------- x transpose: [b][f] -> [f][b]  (f = i*8+k) ----------------
__global__ void k_xt(const float* __restrict__ x){
    __shared__ float t[32][33];
    int f0 = blockIdx.x * 32, b0 = blockIdx.y * 32;
    t[threadIdx.y][threadIdx.x] = x[(size_t)(b0 + threadIdx.y) * FDIM + f0 + threadIdx.x];
    __syncthreads();
    g_xT[(size_t)(f0 + threadIdx.y) * B_TOT + b0 + threadIdx.x] = t[threadIdx.x][threadIdx.y];
}

// ---------------- main pass kernel ----------------
// warp = output capsule n (10 warps), lane = batch (1 batch/thread).
// grid = (36 i-chunks, 8 batch-groups of 32) = 288 CTAs, 2 CTAs/SM.
// PASS 0: c uniform -> pure accumulation (no barriers at all).
// PASS 1: logit = tu.v           -> write b, softmax, accumulate c*tu
// PASS 2: logit = b_old + tu.v   -> write b, softmax, accumulate
// PASS 3: logit = b_old + tu.v   -> softmax, accumulate (no write)
template<int PASS>
__global__ void __launch_bounds__(320, 2) k_pass(){
    __shared__ __align__(16) float ws[2][NCAPS*128];   // double-buffered W tile
    __shared__ __align__(16) float ex[2][32][12];      // ping-pong exp exchange (10 + 2 pad)

    const int tid   = threadIdx.x;
    const int n     = tid >> 5;
    const int lane  = tid & 31;
    const int chunk = blockIdx.x;
    const int bg    = blockIdx.y;
    const int i0    = chunk * I_PER;
    const int b     = bg * 32 + lane;

    if (PASS > 0 && tid < 32){
        ex[0][tid][10] = 0.f; ex[0][tid][11] = 0.f;
        ex[1][tid][10] = 0.f; ex[1][tid][11] = 0.f;
    }

    u64 v[8];
    if (PASS > 0){
        const u64* vp = (const u64*)&g_v[(b*NCAPS + n)*DDIM];
        #pragma unroll
        for (int p = 0; p < 8; p++) v[p] = vp[p];
    }
    u64 s[8];
    #pragma unroll
    for (int p = 0; p < 8; p++) s[p] = 0ull;

    // per-warp W row staging: warp n copies only its own 128-float row.
    // Buffer hazards are warp-private -> cp.async wait_group is enough, no barrier.
    const float* wsrc = g_Wt + ((size_t)(n*IN_CAPS + i0))*128 + lane*4;
    const u32 wdst0 = smemu32(&ws[0][n*128 + lane*4]);
    const u32 wdst1 = smemu32(&ws[1][n*128 + lane*4]);
    cpasync16(wdst0, wsrc);            // stage ii = 0
    cpcommit();

    const float* xp = g_xT + (size_t)i0 * KDIM * B_TOT + b;
    float* bp = g_b + ((size_t)(n*IN_CAPS + i0))*B_TOT + b;

    #pragma unroll 1
    for (int ii = 0; ii < I_PER; ii++){
        // prefetch next W row (empty commit group in the last iteration)
        if (ii + 1 < I_PER) cpasync16((ii & 1) ? wdst0 : wdst1, wsrc + 128);
        cpcommit();
        wsrc += 128;
        cpwait1();                      // current buffer's copy is complete

        float X[8];
        #pragma unroll
        for (int k = 0; k < 8; k++) X[k] = xp[k * B_TOT];   // coalesced, L1-shared
        xp += KDIM * B_TOT;

        // tu[d-pairs] = sum_k Wt[k][:] * x_k   (warp-uniform broadcast LDS)
        const ulonglong2* wrow = (const ulonglong2*)&ws[ii & 1][n*128];
        u64 a[8];
        #pragma unroll
        for (int k = 0; k < 8; k++){
            u64 xk = pk2(X[k], X[k]);
            #pragma unroll
            for (int q = 0; q < 4; q++){
                ulonglong2 w = wrow[k*4 + q];
                if (k == 0){
                    a[2*q]   = fmul2(w.x, xk); a[2*q+1] = fmul2(w.y, xk);
                } else {
                    a[2*q]   = ffma2(w.x, xk, a[2*q]);
                    a[2*q+1] = ffma2(w.y, xk, a[2*q+1]);
                }
            }
        }

        if (PASS == 0){
            #pragma unroll
            for (int p = 0; p < 8; p++) s[p] = fadd2(s[p], a[p]);
        } else {
            u64 d0 = fmul2(a[0], v[0]);
            #pragma unroll
            for (int p = 1; p < 8; p++) d0 = ffma2(a[p], v[p], d0);
            float lo, hi; upk2(d0, lo, hi);
            float logit = lo + hi;
            if (PASS > 1) logit += *bp;
            if (PASS < 3) *bp = logit;
            bp += B_TOT;
            // |logits| stay < ~1 -> exp without max-subtraction is safe
            float e = __expf(logit);
            ex[ii & 1][lane][n] = e;
            __syncthreads();            // the ONLY barrier per i-step
            float4 z0 = *(const float4*)&ex[ii & 1][lane][0];
            float4 z1 = *(const float4*)&ex[ii & 1][lane][4];
            float4 z2 = *(const float4*)&ex[ii & 1][lane][8];
            float Z = ((z0.x + z0.y) + (z0.z + z0.w))
                    + ((z1.x + z1.y) + (z1.z + z1.w))
                    + ((z2.x + z2.y) + (z2.z + z2.w));
            float c = __fdividef(e, Z);
            u64 cc = pk2(c, c);
            #pragma unroll
            for (int p = 0; p < 8; p++) s[p] = ffma2(a[p], cc, s[p]);
        }
    }

    // deterministic per-chunk partials (no atomics)
    float* sp = g_spart + ((size_t)(chunk*B_TOT + b)*NCAPS + n)*DDIM;
    #pragma unroll
    for (int q = 0; q < 4; q++)
        ((ulonglong2*)sp)[q] = make_ulonglong2(s[2*q], s[2*q+1]);
}

// ---------------- reduce partials + squash ----------------
template<bool FINAL>
__global__ void k_reduce(float* __restrict__ out, float scale){
    int g = blockIdx.x * 256 + threadIdx.x;      // over [b][n][d] = 40960
    float s = 0.f;
    #pragma unroll
    for (int c = 0; c < CHUNKS; c++) s += g_spart[(size_t)c*SND + g];
    s *= scale;
    float sq = s * s;
    sq += __shfl_xor_sync(0xffffffffu, sq, 1);
    sq += __shfl_xor_sync(0xffffffffu, sq, 2);
    sq += __shfl_xor_sync(0xffffffffu, sq, 4);
    sq += __shfl_xor_sync(0xffffffffu, sq, 8);
    float nrm = sqrtf(sq);
    float vv = (sq / (1.0f + sq)) * (s / (nrm + 1e-8f));
    if (FINAL) out[g] = vv;
    else       g_v[g] = vv;
}

// ---------------- launch ----------------
extern "C" void kernel_launch(void* const* d_in, const int* in_sizes, int n_in,
                              void* d_out, int out_size){
    const float* x = (const float*)d_in[0];
    const float* W = (const float*)d_in[1];
    if (n_in >= 2 && in_sizes[0] == NCAPS*IN_CAPS*128){   // defensive order swap
        const float* t = x; x = W; W = t;
    }
    float* out = (float*)d_out;

    k_wt<<<(NCAPS*IN_CAPS*128 + 255)/256, 256>>>(W);
    k_xt<<<dim3(FDIM/32, B_TOT/32), dim3(32, 32)>>>(x);

    dim3 pg(CHUNKS, BGROUPS);
    k_pass<0><<<pg, 320>>>();
    k_reduce<false><<<SND/256, 256>>>(nullptr, 0.1f);   // c = softmax(0) = 1/10

    k_pass<1><<<pg, 320>>>();
    k_reduce<false><<<SND/256, 256>>>(nullptr, 1.0f);

    k_pass<2><<<pg, 320>>>();
    k_reduce<false><<<SND/256, 256>>>(nullptr, 1.0f);

    k_pass<3><<<pg, 320>>>();
    k_reduce<true><<<SND/256, 256>>>(out, 1.0f);
}

// round 4
// speedup vs baseline: 1.3164x; 1.0257x over previous
#include <cuda_runtime.h>

typedef unsigned long long u64;
typedef unsigned int u32;

#define B_TOT   256
#define IN_CAPS 1152
#define KDIM    8
#define NCAPS   10
#define DDIM    16
#define CHUNKS  36
#define I_PER   32
#define BGROUPS 8
#define SND     (B_TOT*NCAPS*DDIM)      /* 40960 */
#define FDIM    (IN_CAPS*KDIM)          /* 9216  */

// ---------------- scratch (static device memory, no allocs) ----------------
__device__ float g_Wt[NCAPS*IN_CAPS*128];        // W transposed: [n][i][k][d]
__device__ float g_xT[FDIM*B_TOT];               // x transposed: [i*8+k][b]
__device__ float g_spart[CHUNKS*SND];            // per-chunk partial s
__device__ float g_vc[SND];                      // CUMULATIVE v  [b][n][d]

// ---------------- f32x2 helpers ----------------
__device__ __forceinline__ u64 pk2(float x, float y){
    u64 r; asm("mov.b64 %0,{%1,%2};" : "=l"(r) : "f"(x), "f"(y)); return r;
}
__device__ __forceinline__ void upk2(u64 a, float& x, float& y){
    asm("mov.b64 {%0,%1},%2;" : "=f"(x), "=f"(y) : "l"(a));
}
__device__ __forceinline__ u64 ffma2(u64 a, u64 b, u64 c){
    u64 d; asm("fma.rn.f32x2 %0,%1,%2,%3;" : "=l"(d) : "l"(a), "l"(b), "l"(c)); return d;
}
__device__ __forceinline__ u64 fmul2(u64 a, u64 b){
    u64 d; asm("mul.rn.f32x2 %0,%1,%2;" : "=l"(d) : "l"(a), "l"(b)); return d;
}
__device__ __forceinline__ u64 fadd2(u64 a, u64 b){
    u64 d; asm("add.rn.f32x2 %0,%1,%2;" : "=l"(d) : "l"(a), "l"(b)); return d;
}
__device__ __forceinline__ u32 smemu32(const void* p){
    u32 a; asm("{ .reg .u64 t; cvta.to.shared.u64 t, %1; cvt.u32.u64 %0, t; }" : "=r"(a) : "l"(p));
    return a;
}
__device__ __forceinline__ void cpasync16(u32 dst, const void* src){
    asm volatile("cp.async.ca.shared.global [%0],[%1],16;" :: "r"(dst), "l"(src));
}
__device__ __forceinline__ void cpcommit(){ asm volatile("cp.async.commit_group;"); }
__device__ __forceinline__ void cpwait1(){ asm volatile("cp.async.wait_group 1;"); }

// ---------------- W transpose: [n][i][d][k] -> [n][i][k][d] ----------------
__global__ void k_wt(const float* __restrict__ W){
    int idx = blockIdx.x * 256 + threadIdx.x;
    if (idx >= NCAPS*IN_CAPS*128) return;
    int k  = idx & 7;
    int d  = (idx >> 3) & 15;
    int ni = idx >> 7;
    g_Wt[(ni << 7) | (k << 4) | d] = W[idx];
}

// ---------------- x transpose: [b][f] -> [f][b]  (f = i*8+k) ----------------
__global__ void k_xt(const float* __restrict__ x){
    __shared__ float t[32][33];
    int f0 = blockIdx.x * 32, b0 = blockIdx.y * 32;
    t[threadIdx.y][threadIdx.x] = x[(size_t)(b0 + threadIdx.y) * FDIM + f0 + threadIdx.x];
    __syncthreads();
    g_xT[(size_t)(f0 + threadIdx.y) * B_TOT + b0 + threadIdx.x] = t[threadIdx.x][threadIdx.y];
}

// ---------------- main pass kernel ----------------
// warp = output capsule n (10 warps), lane = batch. grid = (36 chunks, 8 bgroups).
// ROUTE=0 (iteration 0): c uniform -> pure accumulation, zero barriers.
// ROUTE=1 (iterations 1..3): logit = tu . vc  (cumulative v replaces b logits:
//   b_t = tu.(v1+...+v_t), so no global b state is ever needed).
template<int ROUTE>
__global__ void __launch_bounds__(320, 2) k_pass(){
    __shared__ __align__(16) float ws[2][NCAPS*128];   // double-buffered W tile
    __shared__ float ex[2][NCAPS][32];                 // ping-pong exp exchange (transposed)

    const int tid   = threadIdx.x;
    const int n     = tid >> 5;
    const int lane  = tid & 31;
    const int chunk = blockIdx.x;
    const int bg    = blockIdx.y;
    const int i0    = chunk * I_PER;
    const int b     = bg * 32 + lane;

    u64 v[8];
    if (ROUTE){
        const u64* vp = (const u64*)&g_vc[(b*NCAPS + n)*DDIM];
        #pragma unroll
        for (int p = 0; p < 8; p++) v[p] = vp[p];
    }
    u64 s[8];
    #pragma unroll
    for (int p = 0; p < 8; p++) s[p] = 0ull;

    // per-warp W row staging: warp n copies only its own 128-float row.
    // Buffer hazards are warp-private -> cp.async wait_group suffices, no barrier.
    const float* wsrc = g_Wt + ((size_t)(n*IN_CAPS + i0))*128 + lane*4;
    const u32 wdst0 = smemu32(&ws[0][n*128 + lane*4]);
    const u32 wdst1 = smemu32(&ws[1][n*128 + lane*4]);
    cpasync16(wdst0, wsrc);            // stage ii = 0
    cpcommit();

    const float* xp = g_xT + (size_t)i0 * KDIM * B_TOT + b;

    #pragma unroll 1
    for (int ii = 0; ii < I_PER; ii++){
        if (ii + 1 < I_PER) cpasync16((ii & 1) ? wdst0 : wdst1, wsrc + 128);
        cpcommit();
        wsrc += 128;
        cpwait1();                      // current buffer ready

        float X[8];
        #pragma unroll
        for (int k = 0; k < 8; k++) X[k] = xp[k * B_TOT];   // coalesced, L1-shared
        xp += KDIM * B_TOT;

        // tu[d-pairs] = sum_k Wt[k][:] * x_k   (warp-uniform broadcast LDS)
        const ulonglong2* wrow = (const ulonglong2*)&ws[ii & 1][n*128];
        u64 a[8];
        #pragma unroll
        for (int k = 0; k < 8; k++){
            u64 xk = pk2(X[k], X[k]);
            #pragma unroll
            for (int q = 0; q < 4; q++){
                ulonglong2 w = wrow[k*4 + q];
                if (k == 0){
                    a[2*q]   = fmul2(w.x, xk); a[2*q+1] = fmul2(w.y, xk);
                } else {
                    a[2*q]   = ffma2(w.x, xk, a[2*q]);
                    a[2*q+1] = ffma2(w.y, xk, a[2*q+1]);
                }
            }
        }

        if (!ROUTE){
            #pragma unroll
            for (int p = 0; p < 8; p++) s[p] = fadd2(s[p], a[p]);
        } else {
            u64 d0 = fmul2(a[0], v[0]);
            #pragma unroll
            for (int p = 1; p < 8; p++) d0 = ffma2(a[p], v[p], d0);
            float lo, hi; upk2(d0, lo, hi);
            float logit = lo + hi;
            // |logits| stay < ~2 -> exp without max-subtraction is safe
            float e = __expf(logit);
            ex[ii & 1][n][lane] = e;
            __syncthreads();            // the ONLY barrier per i-step
            float Z = ex[ii & 1][0][lane];     // conflict-free column reads
            #pragma unroll
            for (int j = 1; j < NCAPS; j++) Z += ex[ii & 1][j][lane];
            float c = __fdividef(e, Z);
            u64 cc = pk2(c, c);
            #pragma unroll
            for (int p = 0; p < 8; p++) s[p] = ffma2(a[p], cc, s[p]);
        }
    }

    // deterministic per-chunk partials (no atomics)
    float* sp = g_spart + ((size_t)(chunk*B_TOT + b)*NCAPS + n)*DDIM;
    #pragma unroll
    for (int q = 0; q < 4; q++)
        ((ulonglong2*)sp)[q] = make_ulonglong2(s[2*q], s[2*q+1]);
}

// ---------------- reduce partials + squash (warp per (b,n)) ----------------
// MODE 0: vc  = v   (after iteration 0)
// MODE 1: vc += v   (after iterations 1,2)
// MODE 2: out = v   (final)
template<int MODE>
__global__ void k_reduce(float* __restrict__ out, float scale){
    const int gw   = (blockIdx.x * 256 + threadIdx.x) >> 5;   // 0..2559 = (b,n)
    const int lane = threadIdx.x & 31;
    const int d    = lane & 15;
    const int h    = lane >> 4;
    const int bb   = gw / NCAPS, n = gw % NCAPS;
    const size_t base = ((size_t)bb * NCAPS + n) * DDIM + d;

    float s = 0.f;
    #pragma unroll
    for (int c = 0; c < CHUNKS/2; c++)
        s += g_spart[(size_t)(2*c + h) * SND + base];
    s += __shfl_xor_sync(0xffffffffu, s, 16);     // combine chunk halves
    s *= scale;

    float sq = s * s;
    sq += __shfl_xor_sync(0xffffffffu, sq, 1);
    sq += __shfl_xor_sync(0xffffffffu, sq, 2);
    sq += __shfl_xor_sync(0xffffffffu, sq, 4);
    sq += __shfl_xor_sync(0xffffffffu, sq, 8);
    float nrm = sqrtf(sq);
    float vv = (sq / (1.0f + sq)) * (s / (nrm + 1e-8f));

    if (h == 0){
        if (MODE == 0)      g_vc[base] = vv;
        else if (MODE == 1) g_vc[base] += vv;
        else                out[base] = vv;
    }
}

// ---------------- launch ----------------
extern "C" void kernel_launch(void* const* d_in, const int* in_sizes, int n_in,
                              void* d_out, int out_size){
    const float* x = (const float*)d_in[0];
    const float* W = (const float*)d_in[1];
    if (n_in >= 2 && in_sizes[0] == NCAPS*IN_CAPS*128){   // defensive order swap
        const float* t = x; x = W; W = t;
    }
    float* out = (float*)d_out;

    k_wt<<<(NCAPS*IN_CAPS*128 + 255)/256, 256>>>(W);
    k_xt<<<dim3(FDIM/32, B_TOT/32), dim3(32, 32)>>>(x);

    dim3 pg(CHUNKS, BGROUPS);
    const int RB = (B_TOT*NCAPS*32)/256;   // 320 blocks for the reduce

    k_pass<0><<<pg, 320>>>();
    k_reduce<0><<<RB, 256>>>(nullptr, 0.1f);   // c = softmax(0) = 1/10

    k_pass<1><<<pg, 320>>>();
    k_reduce<1><<<RB, 256>>>(nullptr, 1.0f);

    k_pass<1><<<pg, 320>>>();
    k_reduce<1><<<RB, 256>>>(nullptr, 1.0f);

    k_pass<1><<<pg, 320>>>();
    k_reduce<2><<<RB, 256>>>(out, 1.0f);
}

// round 5
// speedup vs baseline: 1.3724x; 1.0425x over previous
#include <cuda_runtime.h>

typedef unsigned long long u64;
typedef unsigned int u32;

#define B_TOT   256
#define IN_CAPS 1152
#define KDIM    8
#define NCAPS   10
#define DDIM    16
#define CHUNKS  36
#define I_PER   32
#define BGROUPS 8
#define SND     (B_TOT*NCAPS*DDIM)      /* 40960 */
#define FDIM    (IN_CAPS*KDIM)          /* 9216  */
#define XBLKS   ((FDIM/32)*(B_TOT/32))  /* 2304  */
#define WELEMS  (NCAPS*IN_CAPS*128)     /* 1474560 */
#define WBLKS   ((WELEMS+1023)/1024)    /* 1440  */

// ---------------- scratch (static device memory, no allocs) ----------------
__device__ float g_Wt[NCAPS*IN_CAPS*128];        // W transposed: [n][i][k][d]
__device__ float g_xT[FDIM*B_TOT];               // x transposed: [i*8+k][b]
__device__ float g_spart[CHUNKS*SND];            // per-chunk partial s
__device__ float g_vc[SND];                      // CUMULATIVE v  [b][n][d]

// ---------------- f32x2 helpers ----------------
__device__ __forceinline__ u64 pk2(float x, float y){
    u64 r; asm("mov.b64 %0,{%1,%2};" : "=l"(r) : "f"(x), "f"(y)); return r;
}
__device__ __forceinline__ void upk2(u64 a, float& x, float& y){
    asm("mov.b64 {%0,%1},%2;" : "=f"(x), "=f"(y) : "l"(a));
}
__device__ __forceinline__ u64 ffma2(u64 a, u64 b, u64 c){
    u64 d; asm("fma.rn.f32x2 %0,%1,%2,%3;" : "=l"(d) : "l"(a), "l"(b), "l"(c)); return d;
}
__device__ __forceinline__ u64 fmul2(u64 a, u64 b){
    u64 d; asm("mul.rn.f32x2 %0,%1,%2;" : "=l"(d) : "l"(a), "l"(b)); return d;
}
__device__ __forceinline__ u64 fadd2(u64 a, u64 b){
    u64 d; asm("add.rn.f32x2 %0,%1,%2;" : "=l"(d) : "l"(a), "l"(b)); return d;
}
__device__ __forceinline__ u32 smemu32(const void* p){
    u32 a; asm("{ .reg .u64 t; cvta.to.shared.u64 t, %1; cvt.u32.u64 %0, t; }" : "=r"(a) : "l"(p));
    return a;
}
__device__ __forceinline__ void cpasync16(u32 dst, const void* src){
    asm volatile("cp.async.ca.shared.global [%0],[%1],16;" :: "r"(dst), "l"(src));
}
__device__ __forceinline__ void cpcommit(){ asm volatile("cp.async.commit_group;"); }
__device__ __forceinline__ void cpwait1(){ asm volatile("cp.async.wait_group 1;"); }

// tu[d-pairs] = sum_k Wt[k][:] * x_k  (warp-uniform broadcast LDS + f32x2 FMA)
__device__ __forceinline__ void tu_compute(const ulonglong2* __restrict__ wrow,
                                           const float* __restrict__ X, u64* a){
    #pragma unroll
    for (int k = 0; k < 8; k++){
        u64 xk = pk2(X[k], X[k]);
        #pragma unroll
        for (int q = 0; q < 4; q++){
            ulonglong2 w = wrow[k*4 + q];
            if (k == 0){
                a[2*q]   = fmul2(w.x, xk); a[2*q+1] = fmul2(w.y, xk);
            } else {
                a[2*q]   = ffma2(w.x, xk, a[2*q]);
                a[2*q+1] = ffma2(w.y, xk, a[2*q+1]);
            }
        }
    }
}

// ---------------- prep: both transposes in ONE kernel ----------------
// blocks [0, XBLKS): x [b][f] -> xT [f][b];  blocks [XBLKS, +WBLKS): W -> Wt
__global__ void k_prep(const float* __restrict__ x, const float* __restrict__ W){
    __shared__ float t[32][33];
    int xb = blockIdx.x;
    int tid = threadIdx.x;
    if (xb < XBLKS){
        int tx = tid & 31, ty = tid >> 5;
        int f0 = (xb % (FDIM/32)) * 32;
        int b0 = (xb / (FDIM/32)) * 32;
        t[ty][tx] = x[(size_t)(b0 + ty) * FDIM + f0 + tx];
        __syncthreads();
        g_xT[(size_t)(f0 + ty) * B_TOT + b0 + tx] = t[tx][ty];
    } else {
        int idx = (xb - XBLKS) * 1024 + tid;
        if (idx < WELEMS){
            int k  = idx & 7;
            int d  = (idx >> 3) & 15;
            int ni = idx >> 7;
            g_Wt[(ni << 7) | (k << 4) | d] = W[idx];
        }
    }
}

// ---------------- main pass kernel ----------------
// warp = capsule n (10 warps), lane = batch. grid = (36 chunks, 8 bgroups), 2 CTAs/SM.
// ROUTE=0: c uniform -> pure accumulation, zero barriers.
// ROUTE=1: logit = tu . vc (cumulative v), ONE barrier per TWO i-steps.
template<int ROUTE>
__global__ void __launch_bounds__(320, 2) k_pass(){
    __shared__ __align__(16) float ws[2][NCAPS*128];   // W slots: even-i / odd-i
    __shared__ float ex[4][NCAPS][32];                 // 4-way ping-pong exchange

    const int tid   = threadIdx.x;
    const int n     = tid >> 5;
    const int lane  = tid & 31;
    const int chunk = blockIdx.x;
    const int bg    = blockIdx.y;
    const int i0    = chunk * I_PER;
    const int b     = bg * 32 + lane;

    u64 v[8];
    if (ROUTE){
        const u64* vp = (const u64*)&g_vc[(b*NCAPS + n)*DDIM];
        #pragma unroll
        for (int p = 0; p < 8; p++) v[p] = vp[p];
    }
    u64 s[8];
    #pragma unroll
    for (int p = 0; p < 8; p++) s[p] = 0ull;

    const float* wsrc = g_Wt + ((size_t)(n*IN_CAPS + i0))*128 + lane*4;
    const u32 wdst0 = smemu32(&ws[0][n*128 + lane*4]);
    const u32 wdst1 = smemu32(&ws[1][n*128 + lane*4]);
    const float* xp = g_xT + (size_t)i0 * KDIM * B_TOT + b;

    if (!ROUTE){
        // -------- iteration 0: no routing, no barriers --------
        cpasync16(wdst0, wsrc); cpcommit();
        #pragma unroll 1
        for (int ii = 0; ii < I_PER; ii++){
            if (ii + 1 < I_PER) cpasync16((ii & 1) ? wdst0 : wdst1, wsrc + 128);
            cpcommit();
            wsrc += 128;
            cpwait1();
            float X[8];
            #pragma unroll
            for (int k = 0; k < 8; k++) X[k] = xp[k * B_TOT];
            xp += KDIM * B_TOT;
            u64 a[8];
            tu_compute((const ulonglong2*)&ws[ii & 1][n*128], X, a);
            #pragma unroll
            for (int p = 0; p < 8; p++) s[p] = fadd2(s[p], a[p]);
        }
    } else {
        // -------- routed iterations: 2 i-steps per barrier --------
        cpasync16(wdst0, wsrc);        cpcommit();   // W(i0+0)
        cpasync16(wdst1, wsrc + 128);  cpcommit();   // W(i0+1)
        #pragma unroll 1
        for (int ii = 0; ii < I_PER; ii += 2){
            const int bufA = ((ii >> 1) & 1) * 2;

            // ---- sub-step A (even i, slot0) ----
            cpwait1();                              // W(ii) ready
            float XA[8];
            #pragma unroll
            for (int k = 0; k < 8; k++) XA[k] = xp[k * B_TOT];
            u64 aA[8];
            tu_compute((const ulonglong2*)&ws[0][n*128], XA, aA);
            u64 dA = fmul2(aA[0], v[0]);
            #pragma unroll
            for (int p = 1; p < 8; p++) dA = ffma2(aA[p], v[p], dA);
            float lA, hA; upk2(dA, lA, hA);
            float eA = __expf(lA + hA);             // |logit| small: no max-sub needed
            ex[bufA][n][lane] = eA;
            if (ii + 2 < I_PER) cpasync16(wdst0, wsrc + 256);   // W(ii+2)
            cpcommit();

            // ---- sub-step B (odd i, slot1) ----
            cpwait1();                              // W(ii+1) ready
            float XB[8];
            #pragma unroll
            for (int k = 0; k < 8; k++) XB[k] = xp[(8 + k) * B_TOT];
            xp += 2 * KDIM * B_TOT;
            u64 aB[8];
            tu_compute((const ulonglong2*)&ws[1][n*128], XB, aB);
            u64 dB = fmul2(aB[0], v[0]);
            #pragma unroll
            for (int p = 1; p < 8; p++) dB = ffma2(aB[p], v[p], dB);
            float lB, hB; upk2(dB, lB, hB);
            float eB = __expf(lB + hB);
            ex[bufA + 1][n][lane] = eB;
            if (ii + 3 < I_PER) cpasync16(wdst1, wsrc + 384);   // W(ii+3)
            cpcommit();
            wsrc += 256;

            __syncthreads();                        // ONE barrier per 2 i-steps

            float ZA = ex[bufA][0][lane], ZB = ex[bufA + 1][0][lane];
            #pragma unroll
            for (int j = 1; j < NCAPS; j++){ ZA += ex[bufA][j][lane]; ZB += ex[bufA + 1][j][lane]; }
            float cA = __fdividef(eA, ZA);
            float cB = __fdividef(eB, ZB);
            u64 ccA = pk2(cA, cA), ccB = pk2(cB, cB);
            #pragma unroll
            for (int p = 0; p < 8; p++){
                s[p] = ffma2(aA[p], ccA, s[p]);
                s[p] = ffma2(aB[p], ccB, s[p]);
            }
        }
    }

    // deterministic per-chunk partials (no atomics)
    float* sp = g_spart + ((size_t)(chunk*B_TOT + b)*NCAPS + n)*DDIM;
    #pragma unroll
    for (int q = 0; q < 4; q++)
        ((ulonglong2*)sp)[q] = make_ulonglong2(s[2*q], s[2*q+1]);
}

// ---------------- reduce partials + squash (2 warps per (b,n)) ----------------
// MODE 0: vc = v ; MODE 1: vc += v ; MODE 2: out = v
template<int MODE>
__global__ void k_reduce(float* __restrict__ out, float scale){
    __shared__ float red[4][2][16];
    const int tid  = threadIdx.x;
    const int wid  = tid >> 5;           // 0..7
    const int lane = tid & 31;
    const int pib  = wid >> 1;           // pair-in-block 0..3
    const int half = wid & 1;
    const int pair = blockIdx.x * 4 + pib;     // (b,n) in [0, 2560)
    const int d    = lane & 15;
    const int hh   = lane >> 4;
    const size_t base = (size_t)pair * DDIM + d;

    float s = 0.f;
    #pragma unroll
    for (int j = 0; j < 9; j++)
        s += g_spart[(size_t)(half*2 + hh + 4*j) * SND + base];
    s += __shfl_xor_sync(0xffffffffu, s, 16);
    if (lane < 16) red[pib][half][d] = s;
    __syncthreads();
    if (half == 0){
        float st = (red[pib][0][d] + red[pib][1][d]) * scale;
        float sq = st * st;
        sq += __shfl_xor_sync(0xffffffffu, sq, 1);
        sq += __shfl_xor_sync(0xffffffffu, sq, 2);
        sq += __shfl_xor_sync(0xffffffffu, sq, 4);
        sq += __shfl_xor_sync(0xffffffffu, sq, 8);
        float nrm = sqrtf(sq);
        float vv = (sq / (1.0f + sq)) * (st / (nrm + 1e-8f));
        if (lane < 16){
            if (MODE == 0)      g_vc[base] = vv;
            else if (MODE == 1) g_vc[base] += vv;
            else                out[base] = vv;
        }
    }
}

// ---------------- launch ----------------
extern "C" void kernel_launch(void* const* d_in, const int* in_sizes, int n_in,
                              void* d_out, int out_size){
    const float* x = (const float*)d_in[0];
    const float* W = (const float*)d_in[1];
    if (n_in >= 2 && in_sizes[0] == WELEMS){   // defensive order swap
        const float* t = x; x = W; W = t;
    }
    float* out = (float*)d_out;

    k_prep<<<XBLKS + WBLKS, 1024>>>(x, W);

    dim3 pg(CHUNKS, BGROUPS);
    const int RB = (B_TOT*NCAPS)/4;    // 640 blocks

    k_pass<0><<<pg, 320>>>();
    k_reduce<0><<<RB, 256>>>(nullptr, 0.1f);   // c = softmax(0) = 1/10

    k_pass<1><<<pg, 320>>>();
    k_reduce<1><<<RB, 256>>>(nullptr, 1.0f);

    k_pass<1><<<pg, 320>>>();
    k_reduce<1><<<RB, 256>>>(nullptr, 1.0f);

    k_pass<1><<<pg, 320>>>();
    k_reduce<2><<<RB, 256>>>(out, 1.0f);
}